// round 1
// baseline (speedup 1.0000x reference)
#include <cuda_runtime.h>

#define NB 16384
#define NN 524288
#define NE 1048576
#define DEMB 128
#define DSTATE 64
#define NSTATES 10

// Scratch (device globals — no allocation allowed)
__device__ float g_logits[NN];
__device__ int   g_starts[NB + 1];

// ---------------- packed fp32x2 helpers ----------------
__device__ __forceinline__ unsigned long long pk2(float x, float y) {
    unsigned long long r;
    asm("mov.b64 %0, {%1, %2};" : "=l"(r) : "f"(x), "f"(y));
    return r;
}
__device__ __forceinline__ float2 upk2(unsigned long long v) {
    float2 r;
    asm("mov.b64 {%0, %1}, %2;" : "=f"(r.x), "=f"(r.y) : "l"(v));
    return r;
}
__device__ __forceinline__ unsigned long long ffma2(unsigned long long a,
                                                    unsigned long long b,
                                                    unsigned long long c) {
    unsigned long long d;
    asm("fma.rn.f32x2 %0, %1, %2, %3;" : "=l"(d) : "l"(a), "l"(b), "l"(c));
    return d;
}

// ---------------- K0: segment starts from sorted batch ----------------
__global__ void k_starts(const int* __restrict__ batch) {
    int n = blockIdx.x * blockDim.x + threadIdx.x;
    if (n >= NN) return;
    int bn = __ldg(&batch[n]);
    if (n == 0) {
        for (int b = 0; b <= bn; b++) g_starts[b] = 0;
    } else {
        int bp = __ldg(&batch[n - 1]);
        for (int b = bp + 1; b <= bn; b++) g_starts[b] = n;
    }
    if (n == NN - 1) {
        for (int b = bn + 1; b <= NB; b++) g_starts[b] = NN;
    }
}

// ---------------- K1: edge_attr_out = [edge_attr | state_emb[state[batch[ei0]]]] ----------------
// One float4 chunk per thread; 24 chunks (96 floats) per edge row.
__global__ __launch_bounds__(256) void k_edges(
    const float4* __restrict__ ea4,   // edge_attr as float4 [E*8]
    const int*    __restrict__ ei0,   // [E]
    const int*    __restrict__ batch, // [N]
    const int*    __restrict__ state, // [B]
    const float4* __restrict__ se4,   // state_emb as float4 [10*16]
    float4*       __restrict__ out4)  // [E*24]
{
    unsigned idx = blockIdx.x * blockDim.x + threadIdx.x;
    if (idx >= NE * 24u) return;
    unsigned e = idx / 24u;
    unsigned c = idx - e * 24u;
    float4 v;
    if (c < 8u) {
        v = __ldg(&ea4[e * 8u + c]);
    } else {
        int src = __ldg(&ei0[e]);
        int b   = __ldg(&batch[src]);
        int s   = __ldg(&state[b]);
        v = __ldg(&se4[(unsigned)s * 16u + (c - 8u)]);
    }
    out4[idx] = v;
}

// ---------------- K2: per-node attention logits ----------------
// logit[n] = leakyrelu(z_atom[n]@W1a + sp[state_of_node]) @ W2 + b2
// warp-per-4-nodes, lane = hidden unit j, packed fp32x2 over k-pairs.
__global__ __launch_bounds__(256) void k_logits(
    const float4* __restrict__ z4,    // z_atom as float4 [N*32]
    const float*  __restrict__ semb,  // [10,64]
    const float*  __restrict__ W1,    // [192,32] row-major
    const float*  __restrict__ b1,    // [32]
    const float*  __restrict__ W2,    // [32]
    const float*  __restrict__ b2,    // [1]
    const int*    __restrict__ state, // [B]
    const int*    __restrict__ batch) // [N]
{
    __shared__ float4 wq[32 * 32];        // wq[kk2*32+j] = W1[(4kk2..4kk2+3)*32+j]  (16KB)
    __shared__ float  sp[NSTATES * 32];   // state part + b1
    __shared__ float  w2s[32];
    __shared__ float4 sa[8][128];         // per-warp staging: 4 rows x 128 floats (16KB)

    int tid = threadIdx.x;

    for (int t = tid; t < 1024; t += 256) {
        int kk2 = t >> 5, j = t & 31;
        float4 w;
        w.x = __ldg(&W1[(4 * kk2 + 0) * 32 + j]);
        w.y = __ldg(&W1[(4 * kk2 + 1) * 32 + j]);
        w.z = __ldg(&W1[(4 * kk2 + 2) * 32 + j]);
        w.w = __ldg(&W1[(4 * kk2 + 3) * 32 + j]);
        wq[t] = w;
    }
    for (int t = tid; t < NSTATES * 32; t += 256) {
        int s = t >> 5, j = t & 31;
        float acc = __ldg(&b1[j]);
        #pragma unroll 8
        for (int m = 0; m < DSTATE; m++)
            acc += __ldg(&semb[s * DSTATE + m]) * __ldg(&W1[(DEMB + m) * 32 + j]);
        sp[t] = acc;
    }
    if (tid < 32) w2s[tid] = __ldg(&W2[tid]);
    __syncthreads();
    float b2v = __ldg(&b2[0]);

    int warpId = tid >> 5, lane = tid & 31;
    float4* saw = sa[warpId];
    unsigned stride = gridDim.x * 8u;

    for (unsigned grp = blockIdx.x * 8u + warpId; grp < NN / 4u; grp += stride) {
        unsigned n0 = grp * 4u;
        // state indices (broadcast loads, L2-resident)
        int s0 = __ldg(&state[__ldg(&batch[n0 + 0])]);
        int s1 = __ldg(&state[__ldg(&batch[n0 + 1])]);
        int s2 = __ldg(&state[__ldg(&batch[n0 + 2])]);
        int s3 = __ldg(&state[__ldg(&batch[n0 + 3])]);
        // stage 4 z_atom rows (coalesced 512B per row)
        float4 r0 = __ldg(&z4[(n0 + 0) * 32u + lane]);
        float4 r1 = __ldg(&z4[(n0 + 1) * 32u + lane]);
        float4 r2 = __ldg(&z4[(n0 + 2) * 32u + lane]);
        float4 r3 = __ldg(&z4[(n0 + 3) * 32u + lane]);
        __syncwarp();   // previous iteration's reads of saw are done
        saw[0 * 32 + lane] = r0;
        saw[1 * 32 + lane] = r1;
        saw[2 * 32 + lane] = r2;
        saw[3 * 32 + lane] = r3;
        __syncwarp();

        unsigned long long acc0 = pk2(sp[s0 * 32 + lane], 0.f);
        unsigned long long acc1 = pk2(sp[s1 * 32 + lane], 0.f);
        unsigned long long acc2 = pk2(sp[s2 * 32 + lane], 0.f);
        unsigned long long acc3 = pk2(sp[s3 * 32 + lane], 0.f);

        #pragma unroll
        for (int kk2 = 0; kk2 < 32; kk2++) {
            float4 wv = wq[kk2 * 32 + lane];
            unsigned long long w01 = pk2(wv.x, wv.y);
            unsigned long long w23 = pk2(wv.z, wv.w);
            float4 a0 = saw[0 * 32 + kk2];
            float4 a1 = saw[1 * 32 + kk2];
            float4 a2 = saw[2 * 32 + kk2];
            float4 a3 = saw[3 * 32 + kk2];
            acc0 = ffma2(pk2(a0.x, a0.y), w01, acc0);
            acc0 = ffma2(pk2(a0.z, a0.w), w23, acc0);
            acc1 = ffma2(pk2(a1.x, a1.y), w01, acc1);
            acc1 = ffma2(pk2(a1.z, a1.w), w23, acc1);
            acc2 = ffma2(pk2(a2.x, a2.y), w01, acc2);
            acc2 = ffma2(pk2(a2.z, a2.w), w23, acc2);
            acc3 = ffma2(pk2(a3.x, a3.y), w01, acc3);
            acc3 = ffma2(pk2(a3.z, a3.w), w23, acc3);
        }

        float2 u0 = upk2(acc0), u1 = upk2(acc1), u2 = upk2(acc2), u3 = upk2(acc3);
        float t0 = u0.x + u0.y; t0 = t0 > 0.f ? t0 : 0.01f * t0;
        float t1 = u1.x + u1.y; t1 = t1 > 0.f ? t1 : 0.01f * t1;
        float t2 = u2.x + u2.y; t2 = t2 > 0.f ? t2 : 0.01f * t2;
        float t3 = u3.x + u3.y; t3 = t3 > 0.f ? t3 : 0.01f * t3;
        float wj = w2s[lane];
        float c0 = t0 * wj, c1 = t1 * wj, c2 = t2 * wj, c3 = t3 * wj;
        #pragma unroll
        for (int off = 16; off; off >>= 1) {
            c0 += __shfl_xor_sync(0xffffffffu, c0, off);
            c1 += __shfl_xor_sync(0xffffffffu, c1, off);
            c2 += __shfl_xor_sync(0xffffffffu, c2, off);
            c3 += __shfl_xor_sync(0xffffffffu, c3, off);
        }
        if (lane == 0) {
            g_logits[n0 + 0] = c0 + b2v;
            g_logits[n0 + 1] = c1 + b2v;
            g_logits[n0 + 2] = c2 + b2v;
            g_logits[n0 + 3] = c3 + b2v;
        }
    }
}

// ---------------- K3: segment softmax + weighted pool + concat z_mol ----------------
__global__ __launch_bounds__(128) void k_pool(
    const float* __restrict__ z_atom, // [N,128]
    const float* __restrict__ z_mol,  // [B,128]
    float*       __restrict__ out)    // x at out[0 .. B*256)
{
    int b = blockIdx.x;
    int tid = threadIdx.x;
    int lane = tid & 31, wid = tid >> 5;
    int lo = g_starts[b], hi = g_starts[b + 1];
    int cnt = hi - lo;

    __shared__ float se[1024];
    __shared__ float red[4];

    // segment max
    float m = -3.402823466e38f;
    for (int i = tid; i < cnt; i += 128) m = fmaxf(m, g_logits[lo + i]);
    #pragma unroll
    for (int off = 16; off; off >>= 1) m = fmaxf(m, __shfl_xor_sync(0xffffffffu, m, off));
    if (lane == 0) red[wid] = m;
    __syncthreads();
    m = fmaxf(fmaxf(red[0], red[1]), fmaxf(red[2], red[3]));
    __syncthreads();

    // exp + segment sum (cache exp values in smem; fallback recompute if huge)
    float s = 0.f;
    for (int i = tid; i < cnt; i += 128) {
        float e = __expf(g_logits[lo + i] - m);
        if (i < 1024) se[i] = e;
        s += e;
    }
    #pragma unroll
    for (int off = 16; off; off >>= 1) s += __shfl_xor_sync(0xffffffffu, s, off);
    if (lane == 0) red[wid] = s;
    __syncthreads();   // also makes se[] visible to all threads
    s = red[0] + red[1] + red[2] + red[3];
    float inv = 1.f / (s + 1e-16f);

    // weighted pool: thread tid owns embedding dim d = tid
    float acc = 0.f;
    const float* za = z_atom + (size_t)lo * 128 + tid;
    for (int n = 0; n < cnt; n++) {
        float e = (n < 1024) ? se[n] : __expf(g_logits[lo + n] - m);
        acc += e * za[(size_t)n * 128];
    }
    out[(size_t)b * 256 + tid]       = z_mol[(size_t)b * 128 + tid];
    out[(size_t)b * 256 + 128 + tid] = acc * inv;
}

// ---------------- launcher ----------------
extern "C" void kernel_launch(void* const* d_in, const int* in_sizes, int n_in,
                              void* d_out, int out_size) {
    const float* edge_attr = (const float*)d_in[0];
    const float* z_mol     = (const float*)d_in[1];
    const float* z_atom    = (const float*)d_in[2];
    const float* state_emb = (const float*)d_in[3];
    const float* W1        = (const float*)d_in[4];
    const float* b1        = (const float*)d_in[5];
    const float* W2        = (const float*)d_in[6];
    const float* b2        = (const float*)d_in[7];
    const int*   state     = (const int*)d_in[8];
    const int*   ei0       = (const int*)d_in[9];
    const int*   batch     = (const int*)d_in[10];
    float* out = (float*)d_out;

    (void)in_sizes; (void)n_in; (void)out_size;

    k_starts<<<(NN + 255) / 256, 256>>>(batch);

    k_edges<<<(NE * 24 + 255) / 256, 256>>>(
        (const float4*)edge_attr, ei0, batch, state,
        (const float4*)state_emb,
        (float4*)(out + (size_t)NB * 256));

    k_logits<<<2048, 256>>>(
        (const float4*)z_atom, state_emb, W1, b1, W2, b2, state, batch);

    k_pool<<<NB, 128>>>(z_atom, z_mol, out);
}